// round 14
// baseline (speedup 1.0000x reference)
#include <cuda_runtime.h>
#include <cstdint>

// GraphConvolution on GB300 — fp16 m16n8k16 mma.sync, issue/LDS-minimized GEMM.
//   k_gemm: 256 threads (8 warps, warp=32m x 64n), 3-stage cp.async (dynamic
//   SMEM), SPLITS=4, one launch for both orientations.
//   GZ=0: A fragments via float2 (identity k-slot permutation, svB packed to
//         match). GZ=1: verified conflict-free scalar path (suB old packing).

#define IN_DIM 128
#define HID    64
#define NMAX   8192
#define SPLITS 4
#define BM     256
#define BK     16

#define AS0_STRIDE 20
#define AS1_STRIDE 264
#define AS_FLOATS  5120
#define BS_U32     512
#define STAGE_BYTES (AS_FLOATS * 4 + BS_U32 * 4)   // 22528
#define SMEM_BYTES  (3 * STAGE_BYTES)              // 67584

// B packed layout (u32): idx = (k/16)*512 + t*128 + h*2 + sel
//  svB (GZ=0): sel0 = k(2t,2t+1) low-first, sel1 = k(2t+8,2t+9)   [identity]
//  suB (GZ=1): sel0 = k(t,t+8),   sel1 = k(t+4,t+12)              [legacy]
__device__ __align__(16) float    g_Wu[IN_DIM * HID];
__device__ __align__(16) float    g_Wv[IN_DIM * HID];
__device__ __align__(16) uint32_t g_suB[NMAX * HID / 2];
__device__ __align__(16) uint32_t g_svB[NMAX * HID / 2];
__device__ __align__(16) float    g_part[2 * SPLITS * NMAX * HID];

__device__ __forceinline__ uint32_t pack_h2(float lo, float hi) {
    uint32_t r;   // cvt.f16x2: first source -> HIGH half
    asm("cvt.rn.f16x2.f32 %0, %1, %2;" : "=r"(r) : "f"(hi), "f"(lo));
    return r;
}
__device__ __forceinline__ void cp16(void* dst_smem, const void* src_gmem) {
    uint32_t d = (uint32_t)__cvta_generic_to_shared(dst_smem);
    asm volatile("cp.async.cg.shared.global [%0], [%1], 16;\n" :: "r"(d), "l"(src_gmem));
}

// ---------------------------------------------------------------------------
__global__ void k_prep(const float* __restrict__ uw, const float* __restrict__ vw,
                       const int* __restrict__ rp) {
    const int r = rp[0];
    const int n = IN_DIM * HID;
    for (int i = blockIdx.x * blockDim.x + threadIdx.x; i < n; i += gridDim.x * blockDim.x) {
        float a = 0.f, b = 0.f;
        for (int c = 0; c <= r; c++) { a += uw[c * n + i]; b += vw[c * n + i]; }
        g_Wu[i] = a; g_Wv[i] = b;
    }
}

// ---------------------------------------------------------------------------
// su/sv = X @ W; packed per-tensor style (see header).
#define WT_STRIDE 132
__global__ __launch_bounds__(256)
void k_feat(const float* __restrict__ u, const float* __restrict__ v, int nu, int nv) {
    __shared__ float Wt[HID * WT_STRIDE];
    __shared__ float Us[32 * IN_DIM];
    const float* X; const float* W; uint32_t* out; int rows;
    const int style_new = blockIdx.y;   // 0: suB legacy, 1: svB identity
    if (blockIdx.y == 0) { X = u; W = g_Wu; out = g_suB; rows = nu; }
    else                 { X = v; W = g_Wv; out = g_svB; rows = nv; }

    const int tid = threadIdx.x;
    const int r0  = blockIdx.x * 32;
    if (r0 >= rows) return;

    for (int i = tid; i < IN_DIM * HID; i += 256) {
        const int k = i >> 6, h = i & 63;
        Wt[h * WT_STRIDE + k] = W[i];
    }
    for (int i = tid; i < 32 * IN_DIM; i += 256)  Us[i] = X[(size_t)r0 * IN_DIM + i];
    __syncthreads();

    const int h   = tid & 63;
    const int q   = tid >> 6;        // 0..3
    const int b16 = q >> 1;
    const int qh  = q & 1;

    // row set handled by this thread (local to the 32-row block)
    int rows8[8];
    if (style_new) {
        #pragma unroll
        for (int i = 0; i < 8; i++) rows8[i] = 16 * b16 + 8 * qh + i;
    } else {
        #pragma unroll
        for (int i = 0; i < 4; i++) { rows8[i] = 16 * b16 + 4 * qh + i; rows8[i + 4] = rows8[i] + 8; }
    }

    float acc[8];
    #pragma unroll
    for (int i = 0; i < 8; i++) acc[i] = 0.f;

    #pragma unroll 4
    for (int k = 0; k < IN_DIM; k += 4) {
        const float4 wq = *(const float4*)&Wt[h * WT_STRIDE + k];
        #pragma unroll
        for (int i = 0; i < 8; i++) {
            const float4 uq = *(const float4*)&Us[rows8[i] * IN_DIM + k];
            acc[i] += uq.x * wq.x + uq.y * wq.y + uq.z * wq.z + uq.w * wq.w;
        }
    }
    const int kb = (r0 >> 4) + b16;
    if (style_new) {
        #pragma unroll
        for (int i = 0; i < 8; i += 2) {
            const int x = 4 * qh + (i >> 1);           // pair (2x, 2x+1)
            out[(size_t)kb * 512 + (x & 3) * 128 + h * 2 + (x >> 2)] = pack_h2(acc[i], acc[i + 1]);
        }
    } else {
        #pragma unroll
        for (int i = 0; i < 4; i++) {
            const int tt = 4 * qh + i;                 // pair (tt, tt+8)-style
            out[(size_t)kb * 512 + (tt & 3) * 128 + h * 2 + (tt >> 2)] = pack_h2(acc[i], acc[i + 4]);
        }
    }
}

// ---------------------------------------------------------------------------
// GZ=0: C[m,h] = sum_k adj[m*nv+k] * sv[k,h]
// GZ=1: C[m,h] = sum_k adj[k*nv+m] * su[k,h]
template <int GZ>
__device__ __forceinline__
void gemm_body(const float* __restrict__ adj, int nu, int nv, char* smem) {
    const int K = GZ ? nu : nv;
    const uint32_t* __restrict__ B = GZ ? g_suB : g_svB;

    constexpr int AS = GZ ? AS1_STRIDE : AS0_STRIDE;

    const int m0     = blockIdx.x * BM;
    const int klen   = K / SPLITS;
    const int k0     = blockIdx.y * klen;
    const int ntiles = klen / BK;

    const int tid  = threadIdx.x;
    const int warp = tid >> 5;
    const int lane = tid & 31;
    const int g    = lane >> 2;
    const int t    = lane & 3;
    const int wm   = warp * 32;

    float acc[2][8][4];
    #pragma unroll
    for (int i = 0; i < 2; i++)
        #pragma unroll
        for (int j = 0; j < 8; j++)
            #pragma unroll
            for (int q = 0; q < 4; q++) acc[i][j][q] = 0.f;

    auto stageA = [&](int s) { return (float*)(smem + s * STAGE_BYTES); };
    auto stageB = [&](int s) { return (uint32_t*)(smem + s * STAGE_BYTES + AS_FLOATS * 4); };

    auto issue = [&](int s, int kt) {
        const int kbase = k0 + kt * BK;
        if (tid < 128)   // B tile: 2KB, 16B per thread
            cp16(&stageB(s)[tid * 4], &B[(size_t)(kbase >> 4) * 512 + tid * 4]);
        float* As = stageA(s);
        #pragma unroll
        for (int i = 0; i < 4; i++) {    // A tile: 16KB, 4 chunks/thread
            const int c = tid + 256 * i;
            if (GZ == 0) {
                const int r = c >> 2, c4 = c & 3;
                cp16(&As[r * AS0_STRIDE + c4 * 4],
                     &adj[(size_t)(m0 + r) * nv + kbase + c4 * 4]);
            } else {
                const int r = c >> 6, c4 = c & 63;
                cp16(&As[r * AS1_STRIDE + c4 * 4],
                     &adj[(size_t)(kbase + r) * nv + m0 + c4 * 4]);
            }
        }
        asm volatile("cp.async.commit_group;\n" ::);
    };

    issue(0, 0);
    issue(1, 1);
    issue(2, 2);

    for (int kt = 0; kt < ntiles; kt++) {
        const int s = kt % 3;
        asm volatile("cp.async.wait_group 2;\n" ::);
        __syncthreads();

        const float*    __restrict__ Ab = stageA(s);
        const uint32_t* __restrict__ Bb = stageB(s);

        uint2 bf[8];
        #pragma unroll
        for (int j = 0; j < 8; j++)
            bf[j] = *(const uint2*)&Bb[t * 128 + (8 * j + g) * 2];

        uint32_t af[2][4];
        #pragma unroll
        for (int i = 0; i < 2; i++) {
            const int mb = wm + i * 16 + g;
            if (GZ == 0) {   // identity slots: float2 pairs (2t,2t+1), (2t+8,2t+9)
                const float2 f0  = *(const float2*)&Ab[(mb)     * AS + 2 * t];
                const float2 f0h = *(const float2*)&Ab[(mb + 8) * AS + 2 * t];
                const float2 f8  = *(const float2*)&Ab[(mb)     * AS + 2 * t + 8];
                const float2 f8h = *(const float2*)&Ab[(mb + 8) * AS + 2 * t + 8];
                af[i][0] = pack_h2(f0.x,  f0.y);
                af[i][1] = pack_h2(f0h.x, f0h.y);
                af[i][2] = pack_h2(f8.x,  f8.y);
                af[i][3] = pack_h2(f8h.x, f8h.y);
            } else {         // legacy slots: conflict-free scalar column reads
                const float lo0  = Ab[(t)      * AS + mb];
                const float lo8  = Ab[(t + 8)  * AS + mb];
                const float hi0  = Ab[(t)      * AS + mb + 8];
                const float hi8  = Ab[(t + 8)  * AS + mb + 8];
                const float lo4  = Ab[(t + 4)  * AS + mb];
                const float lo12 = Ab[(t + 12) * AS + mb];
                const float hi4  = Ab[(t + 4)  * AS + mb + 8];
                const float hi12 = Ab[(t + 12) * AS + mb + 8];
                af[i][0] = pack_h2(lo0, lo8);
                af[i][1] = pack_h2(hi0, hi8);
                af[i][2] = pack_h2(lo4, lo12);
                af[i][3] = pack_h2(hi4, hi12);
            }
        }

        #pragma unroll
        for (int i = 0; i < 2; i++)
            #pragma unroll
            for (int j = 0; j < 8; j++) {
                asm volatile(
                    "mma.sync.aligned.m16n8k16.row.col.f32.f16.f16.f32 "
                    "{%0,%1,%2,%3}, {%4,%5,%6,%7}, {%8,%9}, {%0,%1,%2,%3};"
                    : "+f"(acc[i][j][0]), "+f"(acc[i][j][1]),
                      "+f"(acc[i][j][2]), "+f"(acc[i][j][3])
                    : "r"(af[i][0]), "r"(af[i][1]), "r"(af[i][2]), "r"(af[i][3]),
                      "r"(bf[j].x), "r"(bf[j].y));
            }
        __syncthreads();

        if (kt + 3 < ntiles) issue(s, kt + 3);
        else asm volatile("cp.async.commit_group;\n" ::);   // FIFO padding
    }

    float* __restrict__ P = &g_part[(size_t)((GZ * SPLITS + blockIdx.y) * NMAX) * HID];
    #pragma unroll
    for (int i = 0; i < 2; i++) {
        #pragma unroll
        for (int j = 0; j < 8; j++) {
            const int m = m0 + wm + i * 16 + g;
            const int n = j * 8 + 2 * t;
            *(float2*)&P[(size_t)m * HID + n]       = make_float2(acc[i][j][0], acc[i][j][1]);
            *(float2*)&P[(size_t)(m + 8) * HID + n] = make_float2(acc[i][j][2], acc[i][j][3]);
        }
    }
}

__global__ __launch_bounds__(256, 2)
void k_gemm(const float* __restrict__ adj, int nu, int nv) {
    extern __shared__ __align__(16) char smem[];
    if (blockIdx.z == 0) gemm_body<0>(adj, nu, nv, smem);
    else                 gemm_body<1>(adj, nu, nv, smem);
}

// ---------------------------------------------------------------------------
__global__ void k_final(const float* __restrict__ degree, const float* __restrict__ bias,
                        float* __restrict__ out, int nu, int nv) {
    const int total = (nu + nv) * HID;
    const int idx = blockIdx.x * blockDim.x + threadIdx.x;
    if (idx >= total) return;
    const int row = idx >> 6;
    const int h   = idx & 63;
    const int gg  = (row < nu) ? 0 : 1;
    const int rr  = gg ? (row - nu) : row;
    float s = 0.f;
    #pragma unroll
    for (int sp = 0; sp < SPLITS; sp++)
        s += g_part[((size_t)(gg * SPLITS + sp) * NMAX + rr) * HID + h];
    out[idx] = degree[row] * s + bias[h];
}

// ---------------------------------------------------------------------------
extern "C" void kernel_launch(void* const* d_in, const int* in_sizes, int n_in,
                              void* d_out, int out_size) {
    const float* u      = (const float*)d_in[0];
    const float* v      = (const float*)d_in[1];
    const float* adj    = (const float*)d_in[2];
    const float* degree = (const float*)d_in[3];
    const float* uw     = (const float*)d_in[4];
    const float* vw     = (const float*)d_in[5];
    const float* bias   = (const float*)d_in[6];
    const int*   rp     = (const int*)d_in[7];

    const int nu = in_sizes[0] / IN_DIM;   // 8192
    const int nv = in_sizes[1] / IN_DIM;   // 8192
    float* out = (float*)d_out;

    static bool attr_set = false;
    if (!attr_set) {
        cudaFuncSetAttribute(k_gemm, cudaFuncAttributeMaxDynamicSharedMemorySize, SMEM_BYTES);
        attr_set = true;
    }

    k_prep<<<64, 256>>>(uw, vw, rp);

    dim3 gf(nu / 32, 2);
    k_feat<<<gf, 256>>>(u, v, nu, nv);

    dim3 gg(nu / BM, SPLITS, 2);   // (32, 4, 2) = 256 CTAs
    k_gemm<<<gg, 256, SMEM_BYTES>>>(adj, nu, nv);

    const int total = (nu + nv) * HID;
    k_final<<<(total + 255) / 256, 256>>>(degree, bias, out, nu, nv);
}

// round 15
// speedup vs baseline: 2.0913x; 2.0913x over previous
#include <cuda_runtime.h>
#include <cstdint>

// GraphConvolution on GB300 — fp16 m16n8k16 mma.sync, occupancy-optimized GEMM.
//   BM=128, 4 warps (warp = 32m x 64n): A read once, B dup 4x, smem 24.5KB,
//   acc 64 regs -> 4 CTAs/SM. B stored [j][lane] (2-phase conflict-free uint2).
//   2-stage cp.async, SPLITS=4, one launch for both orientations.

#define IN_DIM 128
#define HID    64
#define NMAX   8192
#define SPLITS 4
#define BM     128
#define BK     16

// A-tile SMEM strides (conflict-free scalar fragment LDS, verified):
//   GZ=0 [m][k] stride 20  (banks (20g+t) mod 32 distinct)
//   GZ=1 [k][m] stride 136 (banks (8t+g)  mod 32 distinct)
#define AS0_STRIDE 20
#define AS1_STRIDE 136
#define AS_FLOATS  2560          // max(128*20, 16*136)
#define BS_U32     512           // 16k x 64h fp16

// B packed layout (u32): idx = (k/16)*512 + j*64 + lane*2 + sel
//   lane = 4g + t (warp lane), j = n-block (h = 8j + g)
//   sel=0: halfs (k = t, t+8); sel=1: halfs (k = t+4, t+12)
// Consumer uint2 load at j*64 + lane*2: banks 2*lane mod 32 -> minimal 2-phase.
__device__ __align__(16) float    g_Wu[IN_DIM * HID];
__device__ __align__(16) float    g_Wv[IN_DIM * HID];
__device__ __align__(16) uint32_t g_suB[NMAX * HID / 2];
__device__ __align__(16) uint32_t g_svB[NMAX * HID / 2];
__device__ __align__(16) float    g_part[2 * SPLITS * NMAX * HID];

__device__ __forceinline__ uint32_t pack_h2(float lo, float hi) {
    uint32_t r;   // cvt.f16x2: first source -> HIGH half
    asm("cvt.rn.f16x2.f32 %0, %1, %2;" : "=r"(r) : "f"(hi), "f"(lo));
    return r;
}
__device__ __forceinline__ void cp16(void* dst_smem, const void* src_gmem) {
    uint32_t d = (uint32_t)__cvta_generic_to_shared(dst_smem);
    asm volatile("cp.async.cg.shared.global [%0], [%1], 16;\n" :: "r"(d), "l"(src_gmem));
}

// ---------------------------------------------------------------------------
__global__ void k_prep(const float* __restrict__ uw, const float* __restrict__ vw,
                       const int* __restrict__ rp) {
    const int r = rp[0];
    const int n = IN_DIM * HID;
    for (int i = blockIdx.x * blockDim.x + threadIdx.x; i < n; i += gridDim.x * blockDim.x) {
        float a = 0.f, b = 0.f;
        for (int c = 0; c <= r; c++) { a += uw[c * n + i]; b += vw[c * n + i]; }
        g_Wu[i] = a; g_Wv[i] = b;
    }
}

// ---------------------------------------------------------------------------
// su/sv = X @ W; each thread: column h, 4 row-pairs (tt, tt+8) of a 16-block.
// Output at (k/16)*512 + (h>>3)*64 + (4*(h&7) + (tt&3))*2 + (tt>>2).
#define WT_STRIDE 132
__global__ __launch_bounds__(256)
void k_feat(const float* __restrict__ u, const float* __restrict__ v, int nu, int nv) {
    __shared__ float Wt[HID * WT_STRIDE];
    __shared__ float Us[32 * IN_DIM];
    const float* X; const float* W; uint32_t* out; int rows;
    if (blockIdx.y == 0) { X = u; W = g_Wu; out = g_suB; rows = nu; }
    else                 { X = v; W = g_Wv; out = g_svB; rows = nv; }

    const int tid = threadIdx.x;
    const int r0  = blockIdx.x * 32;
    if (r0 >= rows) return;

    for (int i = tid; i < IN_DIM * HID; i += 256) {
        const int k = i >> 6, h = i & 63;
        Wt[h * WT_STRIDE + k] = W[i];
    }
    for (int i = tid; i < 32 * IN_DIM; i += 256)  Us[i] = X[(size_t)r0 * IN_DIM + i];
    __syncthreads();

    const int h   = tid & 63;
    const int q   = tid >> 6;        // 0..3
    const int b16 = q >> 1;
    const int qh  = q & 1;

    float accLo[4], accHi[4];
    #pragma unroll
    for (int i = 0; i < 4; i++) { accLo[i] = 0.f; accHi[i] = 0.f; }

    #pragma unroll 4
    for (int k = 0; k < IN_DIM; k += 4) {
        const float4 wq = *(const float4*)&Wt[h * WT_STRIDE + k];
        #pragma unroll
        for (int i = 0; i < 4; i++) {
            const int rl = 16 * b16 + 4 * qh + i;
            const float4 ulo = *(const float4*)&Us[rl * IN_DIM + k];
            const float4 uhi = *(const float4*)&Us[(rl + 8) * IN_DIM + k];
            accLo[i] += ulo.x * wq.x + ulo.y * wq.y + ulo.z * wq.z + ulo.w * wq.w;
            accHi[i] += uhi.x * wq.x + uhi.y * wq.y + uhi.z * wq.z + uhi.w * wq.w;
        }
    }
    const int kb = (r0 >> 4) + b16;
    #pragma unroll
    for (int i = 0; i < 4; i++) {
        const int tt  = 4 * qh + i;          // 0..7
        const int idx = (h >> 3) * 64 + (4 * (h & 7) + (tt & 3)) * 2 + (tt >> 2);
        out[(size_t)kb * 512 + idx] = pack_h2(accLo[i], accHi[i]);
    }
}

// ---------------------------------------------------------------------------
// GZ=0: C[m,h] = sum_k adj[m*nv+k] * sv[k,h]
// GZ=1: C[m,h] = sum_k adj[k*nv+m] * su[k,h]
template <int GZ>
__device__ __forceinline__
void gemm_body(const float* __restrict__ adj, int nu, int nv, char* smem) {
    const int K = GZ ? nu : nv;
    const uint32_t* __restrict__ B = GZ ? g_suB : g_svB;

    constexpr int AS = GZ ? AS1_STRIDE : AS0_STRIDE;
    float* As0 = (float*)smem;
    float* As1 = As0 + AS_FLOATS;
    uint32_t* Bs0 = (uint32_t*)(As1 + AS_FLOATS);
    uint32_t* Bs1 = Bs0 + BS_U32;
    float*    const Asb[2] = { As0, As1 };
    uint32_t* const Bsb[2] = { Bs0, Bs1 };

    const int m0     = blockIdx.x * BM;
    const int klen   = K / SPLITS;
    const int k0     = blockIdx.y * klen;
    const int ntiles = klen / BK;

    const int tid  = threadIdx.x;
    const int warp = tid >> 5;
    const int lane = tid & 31;
    const int g    = lane >> 2;
    const int t    = lane & 3;
    const int wm   = warp * 32;

    float acc[2][8][4];
    #pragma unroll
    for (int i = 0; i < 2; i++)
        #pragma unroll
        for (int j = 0; j < 8; j++)
            #pragma unroll
            for (int q = 0; q < 4; q++) acc[i][j][q] = 0.f;

    auto issue = [&](int s, int kt) {
        const int kbase = k0 + kt * BK;
        // B tile: 2KB packed, 1 chunk per thread
        cp16(&Bsb[s][tid * 4], &B[(size_t)(kbase >> 4) * 512 + tid * 4]);
        // A tile: 8KB, 4 chunks per thread
        #pragma unroll
        for (int i = 0; i < 4; i++) {
            const int c = tid + 128 * i;
            if (GZ == 0) {
                const int r = c >> 2, c4 = c & 3;
                cp16(&Asb[s][r * AS0_STRIDE + c4 * 4],
                     &adj[(size_t)(m0 + r) * nv + kbase + c4 * 4]);
            } else {
                const int r = c >> 5, c4 = c & 31;
                cp16(&Asb[s][r * AS1_STRIDE + c4 * 4],
                     &adj[(size_t)(kbase + r) * nv + m0 + c4 * 4]);
            }
        }
        asm volatile("cp.async.commit_group;\n" ::);
    };

    issue(0, 0);
    issue(1, 1);

    for (int kt = 0; kt < ntiles; kt++) {
        const int s = kt & 1;
        asm volatile("cp.async.wait_group 1;\n" ::);
        __syncthreads();

        const float*    __restrict__ Ab = Asb[s];
        const uint32_t* __restrict__ Bb = Bsb[s];

        // B fragments: 8 uint2 loads, banks 2*lane mod 32 -> minimal 2-phase.
        uint2 bf[8];
        #pragma unroll
        for (int j = 0; j < 8; j++)
            bf[j] = *(const uint2*)&Bb[j * 64 + lane * 2];

        // A fragments: verified conflict-free scalar reads + fp16 packs,
        // legacy slot permutation (t,t+8),(t+4,t+12) matching B's producer.
        uint32_t af[2][4];
        #pragma unroll
        for (int i = 0; i < 2; i++) {
            const int mb = wm + i * 16 + g;
            float lo0, lo8, hi0, hi8, lo4, lo12, hi4, hi12;
            if (GZ == 0) {
                lo0  = Ab[(mb)     * AS + t];      lo8  = Ab[(mb)     * AS + t + 8];
                hi0  = Ab[(mb + 8) * AS + t];      hi8  = Ab[(mb + 8) * AS + t + 8];
                lo4  = Ab[(mb)     * AS + t + 4];  lo12 = Ab[(mb)     * AS + t + 12];
                hi4  = Ab[(mb + 8) * AS + t + 4];  hi12 = Ab[(mb + 8) * AS + t + 12];
            } else {
                lo0  = Ab[(t)      * AS + mb];     lo8  = Ab[(t + 8)  * AS + mb];
                hi0  = Ab[(t)      * AS + mb + 8]; hi8  = Ab[(t + 8)  * AS + mb + 8];
                lo4  = Ab[(t + 4)  * AS + mb];     lo12 = Ab[(t + 12) * AS + mb];
                hi4  = Ab[(t + 4)  * AS + mb + 8]; hi12 = Ab[(t + 12) * AS + mb + 8];
            }
            af[i][0] = pack_h2(lo0, lo8);
            af[i][1] = pack_h2(hi0, hi8);
            af[i][2] = pack_h2(lo4, lo12);
            af[i][3] = pack_h2(hi4, hi12);
        }

        #pragma unroll
        for (int i = 0; i < 2; i++)
            #pragma unroll
            for (int j = 0; j < 8; j++) {
                asm volatile(
                    "mma.sync.aligned.m16n8k16.row.col.f32.f16.f16.f32 "
                    "{%0,%1,%2,%3}, {%4,%5,%6,%7}, {%8,%9}, {%0,%1,%2,%3};"
                    : "+f"(acc[i][j][0]), "+f"(acc[i][j][1]),
                      "+f"(acc[i][j][2]), "+f"(acc[i][j][3])
                    : "r"(af[i][0]), "r"(af[i][1]), "r"(af[i][2]), "r"(af[i][3]),
                      "r"(bf[j].x), "r"(bf[j].y));
            }
        __syncthreads();

        if (kt + 2 < ntiles) issue(s, kt + 2);
        else asm volatile("cp.async.commit_group;\n" ::);   // FIFO padding
    }

    float* __restrict__ P = &g_part[(size_t)((GZ * SPLITS + blockIdx.y) * NMAX) * HID];
    #pragma unroll
    for (int i = 0; i < 2; i++) {
        #pragma unroll
        for (int j = 0; j < 8; j++) {
            const int m = m0 + wm + i * 16 + g;
            const int n = j * 8 + 2 * t;
            *(float2*)&P[(size_t)m * HID + n]       = make_float2(acc[i][j][0], acc[i][j][1]);
            *(float2*)&P[(size_t)(m + 8) * HID + n] = make_float2(acc[i][j][2], acc[i][j][3]);
        }
    }
}

__global__ __launch_bounds__(128, 4)
void k_gemm(const float* __restrict__ adj, int nu, int nv) {
    __shared__ __align__(16) char smem[(2 * AS_FLOATS) * 4 + (2 * BS_U32) * 4];  // 24.5KB
    if (blockIdx.z == 0) gemm_body<0>(adj, nu, nv, smem);
    else                 gemm_body<1>(adj, nu, nv, smem);
}

// ---------------------------------------------------------------------------
__global__ void k_final(const float* __restrict__ degree, const float* __restrict__ bias,
                        float* __restrict__ out, int nu, int nv) {
    const int total = (nu + nv) * HID;
    const int idx = blockIdx.x * blockDim.x + threadIdx.x;
    if (idx >= total) return;
    const int row = idx >> 6;
    const int h   = idx & 63;
    const int gg  = (row < nu) ? 0 : 1;
    const int rr  = gg ? (row - nu) : row;
    float s = 0.f;
    #pragma unroll
    for (int sp = 0; sp < SPLITS; sp++)
        s += g_part[((size_t)(gg * SPLITS + sp) * NMAX + rr) * HID + h];
    out[idx] = degree[row] * s + bias[h];
}

// ---------------------------------------------------------------------------
extern "C" void kernel_launch(void* const* d_in, const int* in_sizes, int n_in,
                              void* d_out, int out_size) {
    const float* u      = (const float*)d_in[0];
    const float* v      = (const float*)d_in[1];
    const float* adj    = (const float*)d_in[2];
    const float* degree = (const float*)d_in[3];
    const float* uw     = (const float*)d_in[4];
    const float* vw     = (const float*)d_in[5];
    const float* bias   = (const float*)d_in[6];
    const int*   rp     = (const int*)d_in[7];

    const int nu = in_sizes[0] / IN_DIM;   // 8192
    const int nv = in_sizes[1] / IN_DIM;   // 8192
    float* out = (float*)d_out;

    k_prep<<<64, 256>>>(uw, vw, rp);

    dim3 gf(nu / 32, 2);
    k_feat<<<gf, 256>>>(u, v, nu, nv);

    dim3 gg(nu / BM, SPLITS, 2);   // (64, 4, 2) = 512 CTAs, one wave @4/SM
    k_gemm<<<gg, 128>>>(adj, nu, nv);

    const int total = (nu + nv) * HID;
    k_final<<<(total + 255) / 256, 256>>>(degree, bias, out, nu, nv);
}